// round 8
// baseline (speedup 1.0000x reference)
#include <cuda_runtime.h>
#include <math.h>

// ---------------------------------------------------------------------------
// SMModel — composed-5x5, packed f32x2, 16px/thread ILP edition.
//  * 64-thread blocks, thread = 4x4 pixels: weight/row LDS amortized over
//    624 fma2 per (ci,kg) -> ~78% fma2 issue share, ILP covers LDS latency.
//  * no forced occupancy (R6 spill lesson); borders/compose as R5.
// ---------------------------------------------------------------------------

#define NC    8
#define HID   20
#define CHG   3

typedef unsigned long long ull;

__device__ __align__(16) float g_buf[5064832];

__device__ __forceinline__ float elu_f(float v) {
    return v > 0.f ? v : (expf(v) - 1.f);
}
__device__ __forceinline__ ull pk(float lo, float hi) {
    ull r; asm("mov.b64 %0, {%1, %2};" : "=l"(r) : "f"(lo), "f"(hi)); return r;
}
__device__ __forceinline__ void upk(ull v, float& lo, float& hi) {
    asm("mov.b64 {%0, %1}, %2;" : "=f"(lo), "=f"(hi) : "l"(v));
}
__device__ __forceinline__ ull fma2(ull a, ull b, ull c) {
    ull d; asm("fma.rn.f32x2 %0, %1, %2, %3;" : "=l"(d) : "l"(a), "l"(b), "l"(c)); return d;
}

// ---------------------------------------------------------------------------
// compose: ALL 13 layers, one launch. (unchanged from R5)
// ---------------------------------------------------------------------------
__global__ void compose_kernel(
    const float* __restrict__ iW1, const float* __restrict__ ib1,
    const float* __restrict__ iW2, const float* __restrict__ ib2,
    const float* __restrict__ bW1, const float* __restrict__ bb1,
    const float* __restrict__ bW2, const float* __restrict__ bb2,
    float* __restrict__ tabW5, float* __restrict__ tabB,
    ull* __restrict__ tabDup, ull* __restrict__ tabBDup)
{
    int idx = blockIdx.x * blockDim.x + threadIdx.x;
    if (idx >= 13 * 5184) return;
    int l = idx / 5184;
    int r0 = idx % 5184;
    int cls = r0 / 576;
    int g = (r0 % 576) / 9, k = r0 % 9;
    if (l == 0 && g >= 8) return;

    const float *W1, *b1, *W2, *b2;
    if (l == 0) { W1 = iW1; b1 = ib1; W2 = iW2; b2 = ib2; }
    else {
        int m = l - 1;
        W1 = bW1 + (size_t)m * 1280 * 9;  b1 = bb1 + (size_t)m * 1280;
        W2 = bW2 + (size_t)m * 576 * 180; b2 = bb2 + (size_t)m * 576;
    }

    float T[25];
#pragma unroll
    for (int j = 0; j < 25; j++) T[j] = 0.f;
    float bias = b2[g * 9 + k];

    for (int q = 0; q < 9; q++) {
        int qy = q / 3 - 1, qx = q % 3 - 1;
        bool vyl = (qy >= 0), vyh = (qy <= 0), vxl = (qx >= 0), vxh = (qx <= 0);
        bool in;
        switch (cls) {
            case 0: in = true; break;
            case 1: in = vyl; break;
            case 2: in = vyh; break;
            case 3: in = vxl; break;
            case 4: in = vxh; break;
            case 5: in = vyl && vxl; break;
            case 6: in = vyl && vxh; break;
            case 7: in = vyh && vxl; break;
            default: in = vyh && vxh; break;
        }
        if (!in) continue;
        for (int c = 0; c < HID; c++) {
            float w2 = W2[((size_t)(g * 9 + k) * HID + c) * 9 + q];
            bias += b1[g * HID + c] * w2;
#pragma unroll
            for (int r = 0; r < 9; r++) {
                int ry = r / 3 - 1, rx = r % 3 - 1;
                T[(qy + ry + 2) * 5 + (qx + rx + 2)] += w2 * W1[(size_t)(g * HID + c) * 9 + r];
            }
        }
    }

    float* To = tabW5 + (size_t)l * 129600 + ((size_t)(cls * 64 + g) * 9 + k) * 25;
#pragma unroll
    for (int j = 0; j < 25; j++) To[j] = T[j];
    tabB[(size_t)l * 5184 + (size_t)(cls * 64 + g) * 9 + k] = bias;

    if (cls == 0) {
        ull* dd = tabDup + (size_t)l * 19200 + (size_t)g * 300;
        int kg = k / 3, j = k % 3;
#pragma unroll
        for (int d = 0; d < 25; d++) dd[d * 12 + kg * 4 + j] = pk(T[d], T[d]);
        tabBDup[(size_t)l * 768 + g * 12 + kg * 4 + j] = pk(bias, bias);
    }
}

// ---------------------------------------------------------------------------
__device__ __forceinline__ void load_row(const ull* __restrict__ spair,
                                         int row, int pqx, ull (&R)[7])
{
    const ull* base = spair + row * 36 + pqx;
    ulonglong2 t0 = *reinterpret_cast<const ulonglong2*>(base);
    ulonglong2 t1 = *reinterpret_cast<const ulonglong2*>(base + 2);
    ulonglong2 t2 = *reinterpret_cast<const ulonglong2*>(base + 4);
    R[0] = t0.x; R[1] = t0.y; R[2] = t1.x; R[3] = t1.y;
    R[4] = t2.x; R[5] = t2.y; R[6] = base[6];
}

// ---------------------------------------------------------------------------
// main + border fused. 64 threads/block, thread = 4 rows x 4 cols.
// ---------------------------------------------------------------------------
__global__ __launch_bounds__(64) void smmain_kernel(
    const float* __restrict__ img0, const float* __restrict__ img1p, const float* __restrict__ img2p,
    const float* __restrict__ xin0, const float* __restrict__ xin1, const float* __restrict__ xin2,
    float* __restrict__ out0, float* __restrict__ out1, float* __restrict__ out2,
    const ull* __restrict__ tabDup, const ull* __restrict__ tabBDup,
    const float* __restrict__ tabW5, const float* __restrict__ tabB,
    int nc_in, int slotBase, int mode)
{
    const int bx = blockIdx.x;
    const int o = blockIdx.y, b = blockIdx.z;
    const int tid = threadIdx.x;
    const int mainX = (mode == 0) ? 16 : 21;

    if (bx >= mainX) {
        // ---------------- border path ----------------
        int bp = (bx - mainX) * 64 + tid;
        int limit = (mode == 0) ? 508 : 884;
        if (bp >= limit) return;
        int s, e;
        if (bp < 508)      { s = 0; e = bp; }
        else if (bp < 760) { s = 1; e = bp - 508; }
        else               { s = 2; e = bp - 760; }
        const float* img = (s == 0) ? img0 : (s == 1) ? img1p : img2p;
        const float* xin = (s == 0) ? xin0 : (s == 1) ? xin1 : xin2;
        float* out = (s == 0) ? out0 : (s == 1) ? out1 : out2;
        const int N = 128 >> s;
        const int slot = slotBase + s;

        int py, px;
        if (e < N)              { py = 0;     px = e; }
        else if (e < 2 * N)     { py = N - 1; px = e - N; }
        else if (e < 3 * N - 2) { py = e - 2 * N + 1;       px = 0; }
        else                    { py = e - (3 * N - 2) + 1; px = N - 1; }

        bool Tt = (py == 0), Bb = (py == N - 1), Ll = (px == 0), Rr = (px == N - 1);
        int cls = Tt ? (Ll ? 5 : (Rr ? 6 : 1))
                     : (Bb ? (Ll ? 7 : (Rr ? 8 : 2)) : (Ll ? 3 : 4));

        float w[25];
        const float* ibp = img + (size_t)b * N * N;
#pragma unroll
        for (int dy = 0; dy < 5; dy++)
#pragma unroll
            for (int dx = 0; dx < 5; dx++) {
                int iy = py - 2 + dy, ix = px - 2 + dx;
                w[dy * 5 + dx] = (iy >= 0 && iy < N && ix >= 0 && ix < N) ? ibp[iy * N + ix] : 0.f;
            }

        float accv = 0.f;
        for (int i = 0; i < nc_in; i++) {
            int g = o * nc_in + i;
            const float* tb = tabW5 + (size_t)slot * 129600 + ((size_t)(cls * 64 + g) * 9) * 25;
            const float* bb = tabB + (size_t)slot * 5184 + (size_t)(cls * 64 + g) * 9;
            const float* xb = xin + ((size_t)b * nc_in + i) * N * N;
            float Kf[9];
#pragma unroll
            for (int k = 0; k < 9; k++) Kf[k] = bb[k];
#pragma unroll
            for (int j = 0; j < 25; j++) {
                float v = w[j];
#pragma unroll
                for (int k = 0; k < 9; k++) Kf[k] += tb[k * 25 + j] * v;
            }
#pragma unroll
            for (int k = 0; k < 9; k++) {
                int yy = py + k / 3 - 1, xx = px + k % 3 - 1;
                float xv = (yy >= 0 && yy < N && xx >= 0 && xx < N) ? xb[yy * N + xx] : 0.f;
                accv += Kf[k] * xv;
            }
        }
        out[((size_t)b * NC + o) * N * N + py * N + px] = elu_f(accv);
        return;
    }

    // ---------------- main (interior) path ----------------
    __shared__ __align__(16) float simg[36 * 36];          // 5184 B
    __shared__ __align__(16) ull   spair[36 * 36];         // 10368 B
    __shared__ __align__(16) float sxs[CHG * 34 * 36];     // 14688 B
    __shared__ __align__(16) ull   sWd[CHG * 300];         // 7200 B
    __shared__ __align__(16) ull   sBd[CHG * 12];          // 288 B

    int s, tile;
    const float *img, *xin;
    float* out;
    if (bx < 16)      { s = 0; tile = bx;      img = img0;  xin = xin0; out = out0; }
    else if (bx < 20) { s = 1; tile = bx - 16; img = img1p; xin = xin1; out = out1; }
    else              { s = 2; tile = bx - 20; img = img2p; xin = xin2; out = out2; }
    const int N = 128 >> s;
    const int tilesX = N / 32;
    const int tx0 = (tile % tilesX) * 32, ty0 = (tile / tilesX) * 32;
    const int slot = slotBase + s;
    const int pqx = (tid & 7) * 4;    // 4 cols per thread
    const int pqy = (tid >> 3) * 4;   // 4 rows per thread

    const float* ib = img + (size_t)b * N * N;
    for (int idx = tid; idx < 36 * 36; idx += 64) {
        int ly = idx / 36, lx = idx % 36;
        int gy = ty0 - 2 + ly, gx = tx0 - 2 + lx;
        simg[idx] = (gy >= 0 && gy < N && gx >= 0 && gx < N) ? ib[gy * N + gx] : 0.f;
    }
    __syncthreads();
    for (int idx = tid; idx < 36 * 35; idx += 64) {
        int ly = idx / 35, lx = idx % 35;
        spair[ly * 36 + lx] = pk(simg[ly * 36 + lx], simg[ly * 36 + lx + 1]);
    }
    // (sync before compute provided by the per-phase post-load barrier)

    ull oacc[4][2];
#pragma unroll
    for (int r = 0; r < 4; r++) { oacc[r][0] = 0ull; oacc[r][1] = 0ull; }

    for (int i0 = 0; i0 < nc_in; i0 += CHG) {
        const int chg = (nc_in - i0 < CHG) ? (nc_in - i0) : CHG;
        __syncthreads();   // previous phase compute done

        // stage chg channels: x tiles, weights, biases
        for (int idx = tid; idx < chg * 1156; idx += 64) {
            int ci = idx / 1156, r = idx % 1156;
            int ly = r / 34, lx = r % 34;
            int gy = ty0 - 1 + ly, gx = tx0 - 1 + lx;
            const float* xb = xin + ((size_t)b * nc_in + (i0 + ci)) * N * N;
            sxs[ci * 1224 + ly * 36 + lx] =
                (gy >= 0 && gy < N && gx >= 0 && gx < N) ? xb[gy * N + gx] : 0.f;
        }
        for (int idx = tid; idx < chg * 300; idx += 64) {
            int ci = idx / 300, j = idx % 300;
            int g = o * nc_in + i0 + ci;
            sWd[ci * 300 + j] = tabDup[(size_t)slot * 19200 + (size_t)g * 300 + j];
        }
        if (tid < chg * 12) {
            int ci = tid / 12, j = tid % 12;
            int g = o * nc_in + i0 + ci;
            sBd[ci * 12 + j] = tabBDup[(size_t)slot * 768 + (size_t)g * 12 + j];
        }
        __syncthreads();

#pragma unroll 1
        for (int ci = 0; ci < chg; ci++) {
            const ull*   wd = sWd + ci * 300;
            const ull*   bd = sBd + ci * 12;
            const float* xc = sxs + ci * 1224;

#pragma unroll 1
            for (int kg = 0; kg < 3; kg++) {
                ull acc[3][4][2];
#pragma unroll
                for (int j = 0; j < 3; j++) {
                    ull bb = bd[kg * 4 + j];
#pragma unroll
                    for (int r = 0; r < 4; r++) { acc[j][r][0] = bb; acc[j][r][1] = bb; }
                }

                const ull* wk = wd + kg * 4;
#pragma unroll
                for (int dy = 0; dy < 5; dy++) {
                    // weight row for this dy: 15 ull, uniform -> broadcast LDS
                    ull w[5][3];
#pragma unroll
                    for (int dx = 0; dx < 5; dx++) {
                        const ull* wp = wk + (dy * 5 + dx) * 12;
                        ulonglong2 t = *reinterpret_cast<const ulonglong2*>(wp);
                        w[dx][0] = t.x; w[dx][1] = t.y; w[dx][2] = wp[2];
                    }
#pragma unroll
                    for (int r = 0; r < 4; r++) {
                        ull R[7];
                        load_row(spair, pqy + r + dy, pqx, R);
#pragma unroll
                        for (int dx = 0; dx < 5; dx++) {
#pragma unroll
                            for (int j = 0; j < 3; j++) {
                                acc[j][r][0] = fma2(R[dx],     w[dx][j], acc[j][r][0]);
                                acc[j][r][1] = fma2(R[dx + 2], w[dx][j], acc[j][r][1]);
                            }
                        }
                    }
                }

                // apply per-pixel 3x3 kernel to x patches (ky = kg, kx = j)
#pragma unroll
                for (int r = 0; r < 4; r++) {
                    const float* xr = xc + (pqy + kg + r) * 36 + pqx;
                    float4 q4 = *reinterpret_cast<const float4*>(xr);
                    float2 q2 = *reinterpret_cast<const float2*>(xr + 4);
                    ull x0 = pk(q4.x, q4.y), x1 = pk(q4.y, q4.z), x2 = pk(q4.z, q4.w);
                    ull x3 = pk(q4.w, q2.x), x4 = pk(q2.x, q2.y);
                    oacc[r][0] = fma2(acc[0][r][0], x0, oacc[r][0]);
                    oacc[r][0] = fma2(acc[1][r][0], x1, oacc[r][0]);
                    oacc[r][0] = fma2(acc[2][r][0], x2, oacc[r][0]);
                    oacc[r][1] = fma2(acc[0][r][1], x2, oacc[r][1]);
                    oacc[r][1] = fma2(acc[1][r][1], x3, oacc[r][1]);
                    oacc[r][1] = fma2(acc[2][r][1], x4, oacc[r][1]);
                }
            }
        }
    }

    float* ob = out + ((size_t)b * NC + o) * N * N;
#pragma unroll
    for (int r = 0; r < 4; r++) {
        int row = ty0 + pqy + r;
        if (row <= 0 || row >= N - 1) continue;
#pragma unroll
        for (int cp = 0; cp < 2; cp++) {
            float lo, hi;
            upk(oacc[r][cp], lo, hi);
            int col = tx0 + pqx + 2 * cp;
            if (col > 0 && col < N - 1)         ob[row * N + col]     = elu_f(lo);
            if (col + 1 > 0 && col + 1 < N - 1) ob[row * N + col + 1] = elu_f(hi);
        }
    }
}

// ---------------------------------------------------------------------------
__global__ void down_kernel(const float* __restrict__ in, float* __restrict__ out,
                            int C, int No)
{
    int idx = blockIdx.x * blockDim.x + threadIdx.x;
    int total = C * No * No;
    if (idx >= total) return;
    int c = idx / (No * No);
    int p = idx % (No * No);
    int h = p / No, w = p % No;
    int Ni = No * 2;
    const float* ib = in + (size_t)c * Ni * Ni;
    float sv = ib[(2 * h) * Ni + 2 * w] + ib[(2 * h) * Ni + 2 * w + 1]
             + ib[(2 * h + 1) * Ni + 2 * w] + ib[(2 * h + 1) * Ni + 2 * w + 1];
    out[idx] = 0.25f * sv;
}

__global__ void combine_kernel(const float* __restrict__ x0,
                               const float* __restrict__ x1,
                               const float* __restrict__ x2,
                               const float* __restrict__ w5, const float* __restrict__ b5,
                               const float* __restrict__ w6, const float* __restrict__ b6,
                               float* __restrict__ out)
{
    int idx = blockIdx.x * blockDim.x + threadIdx.x;
    if (idx >= 8 * 128 * 128) return;
    int b = idx / (128 * 128);
    int p = idx % (128 * 128);
    int h = p / 128, w = p % 128;
    float v[NC];
#pragma unroll
    for (int c = 0; c < NC; c++) {
        v[c] = x0[((size_t)b * NC + c) * 16384 + p]
             + x1[((size_t)b * NC + c) * 4096 + (h >> 1) * 64 + (w >> 1)]
             + x2[((size_t)b * NC + c) * 1024 + (h >> 2) * 32 + (w >> 2)];
    }
    float accv = b6[0];
#pragma unroll
    for (int o = 0; o < NC; o++) {
        float y = b5[o];
#pragma unroll
        for (int c = 0; c < NC; c++) y += w5[o * NC + c] * v[c];
        y = elu_f(y);
        accv += w6[o] * y;
    }
    out[idx] = accv;
}

// ---------------------------------------------------------------------------
extern "C" void kernel_launch(void* const* d_in, const int* in_sizes, int n_in,
                              void* d_out, int out_size)
{
    const float* image = (const float*)d_in[0];
    const float* x_in  = (const float*)d_in[1];
    const float* iW1   = (const float*)d_in[2];
    const float* ib1   = (const float*)d_in[3];
    const float* iW2   = (const float*)d_in[4];
    const float* ib2   = (const float*)d_in[5];
    const float* bW1   = (const float*)d_in[6];
    const float* bb1   = (const float*)d_in[7];
    const float* bW2   = (const float*)d_in[8];
    const float* bb2   = (const float*)d_in[9];
    const float* w5    = (const float*)d_in[10];
    const float* b5    = (const float*)d_in[11];
    const float* w6    = (const float*)d_in[12];
    const float* b6    = (const float*)d_in[13];

    float* base;
    cudaGetSymbolAddress((void**)&base, g_buf);
    float* img1 = base;                        // 32768
    float* img2 = img1 + 32768;                // 8192
    float* x0a  = img2 + 8192;
    float* x0b  = x0a + 1048576;
    float* x1a  = x0b + 1048576;
    float* x1b  = x1a + 262144;
    float* x2a  = x1b + 262144;
    float* x2b  = x2a + 65536;
    float* tabW5 = x2b + 65536;                // 13*129600
    float* tabB  = tabW5 + 13 * 129600;        // 13*5184
    ull*   tabDup  = (ull*)(tabB + 13 * 5184); // 13*19200 ull
    ull*   tabBDup = tabDup + 13 * 19200;      // 13*768 ull

    // all tables upfront (x-independent)
    compose_kernel<<<(13 * 5184 + 127) / 128, 128>>>(
        iW1, ib1, iW2, ib2, bW1, bb1, bW2, bb2, tabW5, tabB, tabDup, tabBDup);

    // image pyramid
    down_kernel<<<(8 * 64 * 64 + 255) / 256, 256>>>(image, img1, 8, 64);
    down_kernel<<<(8 * 32 * 32 + 255) / 256, 256>>>(img1, img2, 8, 32);

    // init block (slot 0, nc_in=1, full-res only) with fused border
    // grid.x = 16 main + ceil(508/64)=8 border
    smmain_kernel<<<dim3(24, 8, 8), 64>>>(image, img1, img2,
        x_in, x_in, x_in, x0a, x0a, x0a, tabDup, tabBDup, tabW5, tabB, 1, 0, 0);

    // downsample x
    down_kernel<<<(64 * 64 * 64 + 255) / 256, 256>>>(x0a, x1a, 64, 64);
    down_kernel<<<(64 * 32 * 32 + 255) / 256, 256>>>(x1a, x2a, 64, 32);

    float *xc = x0a, *xn = x0b;
    float *x1c = x1a, *x1n = x1b;
    float *x2c = x2a, *x2n = x2b;

    for (int t = 0; t < 4; t++) {
        // grid.x = 21 main + ceil(884/64)=14 border
        smmain_kernel<<<dim3(35, 8, 8), 64>>>(image, img1, img2,
            xc, x1c, x2c, xn, x1n, x2n, tabDup, tabBDup, tabW5, tabB,
            8, 1 + 3 * t, 1);
        { float* tp = xc;  xc = xn;   xn = tp; }
        { float* tp = x1c; x1c = x1n; x1n = tp; }
        { float* tp = x2c; x2c = x2n; x2n = tp; }
    }

    combine_kernel<<<(8 * 128 * 128 + 255) / 256, 256>>>(
        xc, x1c, x2c, w5, b5, w6, b6, (float*)d_out);
}

// round 9
// speedup vs baseline: 1.2553x; 1.2553x over previous
#include <cuda_runtime.h>
#include <math.h>

// ---------------------------------------------------------------------------
// SMModel — composed-5x5, packed f32x2, 2x2 px/thread / 256-thread blocks.
//  Small per-thread tile => ~70-reg live set => 24-32 warps/SM without
//  forcing (R6 spill lesson) or register explosion (R7 lesson).
// ---------------------------------------------------------------------------

#define NC    8
#define HID   20
#define CHG   4

typedef unsigned long long ull;

__device__ __align__(16) float g_buf[5064832];

__device__ __forceinline__ float elu_f(float v) {
    return v > 0.f ? v : (expf(v) - 1.f);
}
__device__ __forceinline__ ull pk(float lo, float hi) {
    ull r; asm("mov.b64 %0, {%1, %2};" : "=l"(r) : "f"(lo), "f"(hi)); return r;
}
__device__ __forceinline__ void upk(ull v, float& lo, float& hi) {
    asm("mov.b64 {%0, %1}, %2;" : "=f"(lo), "=f"(hi) : "l"(v));
}
__device__ __forceinline__ ull fma2(ull a, ull b, ull c) {
    ull d; asm("fma.rn.f32x2 %0, %1, %2, %3;" : "=l"(d) : "l"(a), "l"(b), "l"(c)); return d;
}

// ---------------------------------------------------------------------------
// compose: ALL 13 layers, one launch. (unchanged)
// tabW5[l][cls9][64][9][25] f, tabB[l][cls9][64][9] f,
// tabDup[l][64][25*12] ull (cls0 dup pairs, slot d*12+kg*4+j), tabBDup[l][64][12].
// ---------------------------------------------------------------------------
__global__ void compose_kernel(
    const float* __restrict__ iW1, const float* __restrict__ ib1,
    const float* __restrict__ iW2, const float* __restrict__ ib2,
    const float* __restrict__ bW1, const float* __restrict__ bb1,
    const float* __restrict__ bW2, const float* __restrict__ bb2,
    float* __restrict__ tabW5, float* __restrict__ tabB,
    ull* __restrict__ tabDup, ull* __restrict__ tabBDup)
{
    int idx = blockIdx.x * blockDim.x + threadIdx.x;
    if (idx >= 13 * 5184) return;
    int l = idx / 5184;
    int r0 = idx % 5184;
    int cls = r0 / 576;
    int g = (r0 % 576) / 9, k = r0 % 9;
    if (l == 0 && g >= 8) return;

    const float *W1, *b1, *W2, *b2;
    if (l == 0) { W1 = iW1; b1 = ib1; W2 = iW2; b2 = ib2; }
    else {
        int m = l - 1;
        W1 = bW1 + (size_t)m * 1280 * 9;  b1 = bb1 + (size_t)m * 1280;
        W2 = bW2 + (size_t)m * 576 * 180; b2 = bb2 + (size_t)m * 576;
    }

    float T[25];
#pragma unroll
    for (int j = 0; j < 25; j++) T[j] = 0.f;
    float bias = b2[g * 9 + k];

    for (int q = 0; q < 9; q++) {
        int qy = q / 3 - 1, qx = q % 3 - 1;
        bool vyl = (qy >= 0), vyh = (qy <= 0), vxl = (qx >= 0), vxh = (qx <= 0);
        bool in;
        switch (cls) {
            case 0: in = true; break;
            case 1: in = vyl; break;
            case 2: in = vyh; break;
            case 3: in = vxl; break;
            case 4: in = vxh; break;
            case 5: in = vyl && vxl; break;
            case 6: in = vyl && vxh; break;
            case 7: in = vyh && vxl; break;
            default: in = vyh && vxh; break;
        }
        if (!in) continue;
        for (int c = 0; c < HID; c++) {
            float w2 = W2[((size_t)(g * 9 + k) * HID + c) * 9 + q];
            bias += b1[g * HID + c] * w2;
#pragma unroll
            for (int r = 0; r < 9; r++) {
                int ry = r / 3 - 1, rx = r % 3 - 1;
                T[(qy + ry + 2) * 5 + (qx + rx + 2)] += w2 * W1[(size_t)(g * HID + c) * 9 + r];
            }
        }
    }

    float* To = tabW5 + (size_t)l * 129600 + ((size_t)(cls * 64 + g) * 9 + k) * 25;
#pragma unroll
    for (int j = 0; j < 25; j++) To[j] = T[j];
    tabB[(size_t)l * 5184 + (size_t)(cls * 64 + g) * 9 + k] = bias;

    if (cls == 0) {
        ull* dd = tabDup + (size_t)l * 19200 + (size_t)g * 300;
        int kg = k / 3, j = k % 3;
#pragma unroll
        for (int d = 0; d < 25; d++) dd[d * 12 + kg * 4 + j] = pk(T[d], T[d]);
        tabBDup[(size_t)l * 768 + g * 12 + kg * 4 + j] = pk(bias, bias);
    }
}

// ---------------------------------------------------------------------------
// row pair load: 5 adjacent pairs starting at pqx (even) -> 2x LDS.128 + LDS.64
// ---------------------------------------------------------------------------
__device__ __forceinline__ void load_row5(const ull* __restrict__ spair,
                                          int row, int pqx, ull (&R)[5])
{
    const ull* base = spair + row * 36 + pqx;
    ulonglong2 t0 = *reinterpret_cast<const ulonglong2*>(base);
    ulonglong2 t1 = *reinterpret_cast<const ulonglong2*>(base + 2);
    R[0] = t0.x; R[1] = t0.y; R[2] = t1.x; R[3] = t1.y; R[4] = base[4];
}

// one dy step: 5 dx x 3 j x (2 rows x 1 colpair)
__device__ __forceinline__ void conv_step5(const ull* __restrict__ wrow,
                                           const ull (&R)[5], const ull (&S)[5],
                                           ull (&acc)[3][2])
{
#pragma unroll
    for (int dx = 0; dx < 5; dx++) {
        const ull* wp = wrow + dx * 12;
        ulonglong2 t = *reinterpret_cast<const ulonglong2*>(wp);
        ull w0 = t.x, w1 = t.y, w2 = wp[2];
        acc[0][0] = fma2(R[dx], w0, acc[0][0]);
        acc[0][1] = fma2(S[dx], w0, acc[0][1]);
        acc[1][0] = fma2(R[dx], w1, acc[1][0]);
        acc[1][1] = fma2(S[dx], w1, acc[1][1]);
        acc[2][0] = fma2(R[dx], w2, acc[2][0]);
        acc[2][1] = fma2(S[dx], w2, acc[2][1]);
    }
}

// ---------------------------------------------------------------------------
// main + border fused. 256 threads/block, thread = 2 rows x 2 cols.
// ---------------------------------------------------------------------------
__global__ __launch_bounds__(256) void smmain_kernel(
    const float* __restrict__ img0, const float* __restrict__ img1p, const float* __restrict__ img2p,
    const float* __restrict__ xin0, const float* __restrict__ xin1, const float* __restrict__ xin2,
    float* __restrict__ out0, float* __restrict__ out1, float* __restrict__ out2,
    const ull* __restrict__ tabDup, const ull* __restrict__ tabBDup,
    const float* __restrict__ tabW5, const float* __restrict__ tabB,
    int nc_in, int slotBase, int mode)
{
    const int bx = blockIdx.x;
    const int o = blockIdx.y, b = blockIdx.z;
    const int tid = threadIdx.x;
    const int mainX = (mode == 0) ? 16 : 21;

    if (bx >= mainX) {
        // ---------------- border path ----------------
        int bp = (bx - mainX) * 256 + tid;
        int limit = (mode == 0) ? 508 : 884;
        if (bp >= limit) return;
        int s, e;
        if (bp < 508)      { s = 0; e = bp; }
        else if (bp < 760) { s = 1; e = bp - 508; }
        else               { s = 2; e = bp - 760; }
        const float* img = (s == 0) ? img0 : (s == 1) ? img1p : img2p;
        const float* xin = (s == 0) ? xin0 : (s == 1) ? xin1 : xin2;
        float* out = (s == 0) ? out0 : (s == 1) ? out1 : out2;
        const int N = 128 >> s;
        const int slot = slotBase + s;

        int py, px;
        if (e < N)              { py = 0;     px = e; }
        else if (e < 2 * N)     { py = N - 1; px = e - N; }
        else if (e < 3 * N - 2) { py = e - 2 * N + 1;       px = 0; }
        else                    { py = e - (3 * N - 2) + 1; px = N - 1; }

        bool Tt = (py == 0), Bb = (py == N - 1), Ll = (px == 0), Rr = (px == N - 1);
        int cls = Tt ? (Ll ? 5 : (Rr ? 6 : 1))
                     : (Bb ? (Ll ? 7 : (Rr ? 8 : 2)) : (Ll ? 3 : 4));

        float w[25];
        const float* ibp = img + (size_t)b * N * N;
#pragma unroll
        for (int dy = 0; dy < 5; dy++)
#pragma unroll
            for (int dx = 0; dx < 5; dx++) {
                int iy = py - 2 + dy, ix = px - 2 + dx;
                w[dy * 5 + dx] = (iy >= 0 && iy < N && ix >= 0 && ix < N) ? ibp[iy * N + ix] : 0.f;
            }

        float accv = 0.f;
        for (int i = 0; i < nc_in; i++) {
            int g = o * nc_in + i;
            const float* tb = tabW5 + (size_t)slot * 129600 + ((size_t)(cls * 64 + g) * 9) * 25;
            const float* bb = tabB + (size_t)slot * 5184 + (size_t)(cls * 64 + g) * 9;
            const float* xb = xin + ((size_t)b * nc_in + i) * N * N;
            float Kf[9];
#pragma unroll
            for (int k = 0; k < 9; k++) Kf[k] = bb[k];
#pragma unroll
            for (int j = 0; j < 25; j++) {
                float v = w[j];
#pragma unroll
                for (int k = 0; k < 9; k++) Kf[k] += tb[k * 25 + j] * v;
            }
#pragma unroll
            for (int k = 0; k < 9; k++) {
                int yy = py + k / 3 - 1, xx = px + k % 3 - 1;
                float xv = (yy >= 0 && yy < N && xx >= 0 && xx < N) ? xb[yy * N + xx] : 0.f;
                accv += Kf[k] * xv;
            }
        }
        out[((size_t)b * NC + o) * N * N + py * N + px] = elu_f(accv);
        return;
    }

    // ---------------- main (interior) path ----------------
    __shared__ __align__(16) float simg[36 * 36];          // 5184 B
    __shared__ __align__(16) ull   spair[36 * 36];         // 10368 B
    __shared__ __align__(16) float sxs[CHG * 34 * 36];     // 19584 B
    __shared__ __align__(16) ull   sWd[CHG * 300];         // 9600 B
    __shared__ __align__(16) ull   sBd[CHG * 12];          // 384 B  -> 45120 total

    int s, tile;
    const float *img, *xin;
    float* out;
    if (bx < 16)      { s = 0; tile = bx;      img = img0;  xin = xin0; out = out0; }
    else if (bx < 20) { s = 1; tile = bx - 16; img = img1p; xin = xin1; out = out1; }
    else              { s = 2; tile = bx - 20; img = img2p; xin = xin2; out = out2; }
    const int N = 128 >> s;
    const int tilesX = N / 32;
    const int tx0 = (tile % tilesX) * 32, ty0 = (tile / tilesX) * 32;
    const int slot = slotBase + s;
    const int pqx = (tid & 15) * 2;   // 2 cols per thread (even)
    const int pqy = (tid >> 4) * 2;   // 2 rows per thread

    const float* ib = img + (size_t)b * N * N;
    for (int idx = tid; idx < 36 * 36; idx += 256) {
        int ly = idx / 36, lx = idx % 36;
        int gy = ty0 - 2 + ly, gx = tx0 - 2 + lx;
        simg[idx] = (gy >= 0 && gy < N && gx >= 0 && gx < N) ? ib[gy * N + gx] : 0.f;
    }
    __syncthreads();
    for (int idx = tid; idx < 36 * 35; idx += 256) {
        int ly = idx / 35, lx = idx % 35;
        spair[ly * 36 + lx] = pk(simg[ly * 36 + lx], simg[ly * 36 + lx + 1]);
    }
    // (sync before compute provided by the per-phase post-load barrier)

    ull oacc[2];
    oacc[0] = 0ull; oacc[1] = 0ull;

    for (int i0 = 0; i0 < nc_in; i0 += CHG) {
        const int chg = (nc_in - i0 < CHG) ? (nc_in - i0) : CHG;
        __syncthreads();   // previous phase compute done

        // stage chg channels: x tiles, weights, biases
        for (int idx = tid; idx < chg * 1156; idx += 256) {
            int ci = idx / 1156, r = idx % 1156;
            int ly = r / 34, lx = r % 34;
            int gy = ty0 - 1 + ly, gx = tx0 - 1 + lx;
            const float* xb = xin + ((size_t)b * nc_in + (i0 + ci)) * N * N;
            sxs[ci * 1224 + ly * 36 + lx] =
                (gy >= 0 && gy < N && gx >= 0 && gx < N) ? xb[gy * N + gx] : 0.f;
        }
        for (int idx = tid; idx < chg * 300; idx += 256) {
            int ci = idx / 300, j = idx % 300;
            int g = o * nc_in + i0 + ci;
            sWd[ci * 300 + j] = tabDup[(size_t)slot * 19200 + (size_t)g * 300 + j];
        }
        if (tid < chg * 12) {
            int ci = tid / 12, j = tid % 12;
            int g = o * nc_in + i0 + ci;
            sBd[ci * 12 + j] = tabBDup[(size_t)slot * 768 + (size_t)g * 12 + j];
        }
        __syncthreads();

#pragma unroll 1
        for (int ci = 0; ci < chg; ci++) {
            const ull*   wd = sWd + ci * 300;
            const ull*   bd = sBd + ci * 12;
            const float* xc = sxs + ci * 1224;

#pragma unroll 1
            for (int kg = 0; kg < 3; kg++) {
                ull acc[3][2];
#pragma unroll
                for (int j = 0; j < 3; j++) {
                    ull bb = bd[kg * 4 + j];
                    acc[j][0] = bb; acc[j][1] = bb;
                }

                const ull* wk = wd + kg * 4;
                ull A[5], B[5];
                load_row5(spair, pqy,     pqx, A);
                load_row5(spair, pqy + 1, pqx, B);
                conv_step5(wk,       A, B, acc);
                load_row5(spair, pqy + 2, pqx, A);
                conv_step5(wk + 60,  B, A, acc);
                load_row5(spair, pqy + 3, pqx, B);
                conv_step5(wk + 120, A, B, acc);
                load_row5(spair, pqy + 4, pqx, A);
                conv_step5(wk + 180, B, A, acc);
                load_row5(spair, pqy + 5, pqx, B);
                conv_step5(wk + 240, A, B, acc);

                // apply: x[pqx .. pqx+3] per row via 2x float2 (8B aligned)
#pragma unroll
                for (int rr = 0; rr < 2; rr++) {
                    const float* xr = xc + (pqy + kg + rr) * 36 + pqx;
                    float2 a2 = *reinterpret_cast<const float2*>(xr);
                    float2 b2 = *reinterpret_cast<const float2*>(xr + 2);
                    oacc[rr] = fma2(acc[0][rr], pk(a2.x, a2.y), oacc[rr]);
                    oacc[rr] = fma2(acc[1][rr], pk(a2.y, b2.x), oacc[rr]);
                    oacc[rr] = fma2(acc[2][rr], pk(b2.x, b2.y), oacc[rr]);
                }
            }
        }
    }

    float* ob = out + ((size_t)b * NC + o) * N * N;
#pragma unroll
    for (int sy = 0; sy < 2; sy++) {
        float lo, hi;
        upk(oacc[sy], lo, hi);
        int row = ty0 + pqy + sy, col = tx0 + pqx;
        if (row > 0 && row < N - 1) {
            if (col > 0 && col < N - 1)         ob[row * N + col]     = elu_f(lo);
            if (col + 1 > 0 && col + 1 < N - 1) ob[row * N + col + 1] = elu_f(hi);
        }
    }
}

// ---------------------------------------------------------------------------
__global__ void down_kernel(const float* __restrict__ in, float* __restrict__ out,
                            int C, int No)
{
    int idx = blockIdx.x * blockDim.x + threadIdx.x;
    int total = C * No * No;
    if (idx >= total) return;
    int c = idx / (No * No);
    int p = idx % (No * No);
    int h = p / No, w = p % No;
    int Ni = No * 2;
    const float* ib = in + (size_t)c * Ni * Ni;
    float sv = ib[(2 * h) * Ni + 2 * w] + ib[(2 * h) * Ni + 2 * w + 1]
             + ib[(2 * h + 1) * Ni + 2 * w] + ib[(2 * h + 1) * Ni + 2 * w + 1];
    out[idx] = 0.25f * sv;
}

__global__ void combine_kernel(const float* __restrict__ x0,
                               const float* __restrict__ x1,
                               const float* __restrict__ x2,
                               const float* __restrict__ w5, const float* __restrict__ b5,
                               const float* __restrict__ w6, const float* __restrict__ b6,
                               float* __restrict__ out)
{
    int idx = blockIdx.x * blockDim.x + threadIdx.x;
    if (idx >= 8 * 128 * 128) return;
    int b = idx / (128 * 128);
    int p = idx % (128 * 128);
    int h = p / 128, w = p % 128;
    float v[NC];
#pragma unroll
    for (int c = 0; c < NC; c++) {
        v[c] = x0[((size_t)b * NC + c) * 16384 + p]
             + x1[((size_t)b * NC + c) * 4096 + (h >> 1) * 64 + (w >> 1)]
             + x2[((size_t)b * NC + c) * 1024 + (h >> 2) * 32 + (w >> 2)];
    }
    float accv = b6[0];
#pragma unroll
    for (int o = 0; o < NC; o++) {
        float y = b5[o];
#pragma unroll
        for (int c = 0; c < NC; c++) y += w5[o * NC + c] * v[c];
        y = elu_f(y);
        accv += w6[o] * y;
    }
    out[idx] = accv;
}

// ---------------------------------------------------------------------------
extern "C" void kernel_launch(void* const* d_in, const int* in_sizes, int n_in,
                              void* d_out, int out_size)
{
    const float* image = (const float*)d_in[0];
    const float* x_in  = (const float*)d_in[1];
    const float* iW1   = (const float*)d_in[2];
    const float* ib1   = (const float*)d_in[3];
    const float* iW2   = (const float*)d_in[4];
    const float* ib2   = (const float*)d_in[5];
    const float* bW1   = (const float*)d_in[6];
    const float* bb1   = (const float*)d_in[7];
    const float* bW2   = (const float*)d_in[8];
    const float* bb2   = (const float*)d_in[9];
    const float* w5    = (const float*)d_in[10];
    const float* b5    = (const float*)d_in[11];
    const float* w6    = (const float*)d_in[12];
    const float* b6    = (const float*)d_in[13];

    float* base;
    cudaGetSymbolAddress((void**)&base, g_buf);
    float* img1 = base;
    float* img2 = img1 + 32768;
    float* x0a  = img2 + 8192;
    float* x0b  = x0a + 1048576;
    float* x1a  = x0b + 1048576;
    float* x1b  = x1a + 262144;
    float* x2a  = x1b + 262144;
    float* x2b  = x2a + 65536;
    float* tabW5 = x2b + 65536;                // 13*129600
    float* tabB  = tabW5 + 13 * 129600;        // 13*5184
    ull*   tabDup  = (ull*)(tabB + 13 * 5184); // 13*19200 ull
    ull*   tabBDup = tabDup + 13 * 19200;      // 13*768 ull

    // all tables upfront (x-independent)
    compose_kernel<<<(13 * 5184 + 127) / 128, 128>>>(
        iW1, ib1, iW2, ib2, bW1, bb1, bW2, bb2, tabW5, tabB, tabDup, tabBDup);

    // image pyramid
    down_kernel<<<(8 * 64 * 64 + 255) / 256, 256>>>(image, img1, 8, 64);
    down_kernel<<<(8 * 32 * 32 + 255) / 256, 256>>>(img1, img2, 8, 32);

    // init block (slot 0, nc_in=1, full-res only) with fused border
    // grid.x = 16 main + ceil(508/256)=2 border
    smmain_kernel<<<dim3(18, 8, 8), 256>>>(image, img1, img2,
        x_in, x_in, x_in, x0a, x0a, x0a, tabDup, tabBDup, tabW5, tabB, 1, 0, 0);

    // downsample x
    down_kernel<<<(64 * 64 * 64 + 255) / 256, 256>>>(x0a, x1a, 64, 64);
    down_kernel<<<(64 * 32 * 32 + 255) / 256, 256>>>(x1a, x2a, 64, 32);

    float *xc = x0a, *xn = x0b;
    float *x1c = x1a, *x1n = x1b;
    float *x2c = x2a, *x2n = x2b;

    for (int t = 0; t < 4; t++) {
        // grid.x = 21 main + ceil(884/256)=4 border
        smmain_kernel<<<dim3(25, 8, 8), 256>>>(image, img1, img2,
            xc, x1c, x2c, xn, x1n, x2n, tabDup, tabBDup, tabW5, tabB,
            8, 1 + 3 * t, 1);
        { float* tp = xc;  xc = xn;   xn = tp; }
        { float* tp = x1c; x1c = x1n; x1n = tp; }
        { float* tp = x2c; x2c = x2n; x2n = tp; }
    }

    combine_kernel<<<(8 * 128 * 128 + 255) / 256, 256>>>(
        xc, x1c, x2c, w5, b5, w6, b6, (float*)d_out);
}

// round 10
// speedup vs baseline: 1.3270x; 1.0571x over previous
#include <cuda_runtime.h>
#include <math.h>

// ---------------------------------------------------------------------------
// SMModel — composed-5x5, packed f32x2, unified 9-k accumulator pass.
//  * rows loaded ONCE per channel (was 3x, once per kg)
//  * weights amortized over 18 fma2 per load packet (was 6)
//  * simg float stage removed; spair built straight from gmem
// ---------------------------------------------------------------------------

#define NC    8
#define HID   20
#define CHG   4

typedef unsigned long long ull;

__device__ __align__(16) float g_buf[5064832];

__device__ __forceinline__ float elu_f(float v) {
    return v > 0.f ? v : (expf(v) - 1.f);
}
__device__ __forceinline__ ull pk(float lo, float hi) {
    ull r; asm("mov.b64 %0, {%1, %2};" : "=l"(r) : "f"(lo), "f"(hi)); return r;
}
__device__ __forceinline__ void upk(ull v, float& lo, float& hi) {
    asm("mov.b64 {%0, %1}, %2;" : "=f"(lo), "=f"(hi) : "l"(v));
}
__device__ __forceinline__ ull fma2(ull a, ull b, ull c) {
    ull d; asm("fma.rn.f32x2 %0, %1, %2, %3;" : "=l"(d) : "l"(a), "l"(b), "l"(c)); return d;
}

// ---------------------------------------------------------------------------
// compose: ALL 13 layers, one launch.
// tabW5[l][cls9][64][9][25] f, tabB[l][cls9][64][9] f,
// tabDup[l][64][25*12] ull (cls0 pairs, slot d*12+k, k=0..8), tabBDup[l][64][12].
// ---------------------------------------------------------------------------
__global__ void compose_kernel(
    const float* __restrict__ iW1, const float* __restrict__ ib1,
    const float* __restrict__ iW2, const float* __restrict__ ib2,
    const float* __restrict__ bW1, const float* __restrict__ bb1,
    const float* __restrict__ bW2, const float* __restrict__ bb2,
    float* __restrict__ tabW5, float* __restrict__ tabB,
    ull* __restrict__ tabDup, ull* __restrict__ tabBDup)
{
    int idx = blockIdx.x * blockDim.x + threadIdx.x;
    if (idx >= 13 * 5184) return;
    int l = idx / 5184;
    int r0 = idx % 5184;
    int cls = r0 / 576;
    int g = (r0 % 576) / 9, k = r0 % 9;
    if (l == 0 && g >= 8) return;

    const float *W1, *b1, *W2, *b2;
    if (l == 0) { W1 = iW1; b1 = ib1; W2 = iW2; b2 = ib2; }
    else {
        int m = l - 1;
        W1 = bW1 + (size_t)m * 1280 * 9;  b1 = bb1 + (size_t)m * 1280;
        W2 = bW2 + (size_t)m * 576 * 180; b2 = bb2 + (size_t)m * 576;
    }

    float T[25];
#pragma unroll
    for (int j = 0; j < 25; j++) T[j] = 0.f;
    float bias = b2[g * 9 + k];

    for (int q = 0; q < 9; q++) {
        int qy = q / 3 - 1, qx = q % 3 - 1;
        bool vyl = (qy >= 0), vyh = (qy <= 0), vxl = (qx >= 0), vxh = (qx <= 0);
        bool in;
        switch (cls) {
            case 0: in = true; break;
            case 1: in = vyl; break;
            case 2: in = vyh; break;
            case 3: in = vxl; break;
            case 4: in = vxh; break;
            case 5: in = vyl && vxl; break;
            case 6: in = vyl && vxh; break;
            case 7: in = vyh && vxl; break;
            default: in = vyh && vxh; break;
        }
        if (!in) continue;
        for (int c = 0; c < HID; c++) {
            float w2 = W2[((size_t)(g * 9 + k) * HID + c) * 9 + q];
            bias += b1[g * HID + c] * w2;
#pragma unroll
            for (int r = 0; r < 9; r++) {
                int ry = r / 3 - 1, rx = r % 3 - 1;
                T[(qy + ry + 2) * 5 + (qx + rx + 2)] += w2 * W1[(size_t)(g * HID + c) * 9 + r];
            }
        }
    }

    float* To = tabW5 + (size_t)l * 129600 + ((size_t)(cls * 64 + g) * 9 + k) * 25;
#pragma unroll
    for (int j = 0; j < 25; j++) To[j] = T[j];
    tabB[(size_t)l * 5184 + (size_t)(cls * 64 + g) * 9 + k] = bias;

    if (cls == 0) {
        ull* dd = tabDup + (size_t)l * 19200 + (size_t)g * 300;
#pragma unroll
        for (int d = 0; d < 25; d++) dd[d * 12 + k] = pk(T[d], T[d]);
        tabBDup[(size_t)l * 768 + g * 12 + k] = pk(bias, bias);
    }
}

// ---------------------------------------------------------------------------
// row pair load: 5 adjacent pairs starting at pqx (even) -> 2x LDS.128 + LDS.64
// ---------------------------------------------------------------------------
__device__ __forceinline__ void load_row5(const ull* __restrict__ spair,
                                          int row, int pqx, ull (&R)[5])
{
    const ull* base = spair + row * 36 + pqx;
    ulonglong2 t0 = *reinterpret_cast<const ulonglong2*>(base);
    ulonglong2 t1 = *reinterpret_cast<const ulonglong2*>(base + 2);
    R[0] = t0.x; R[1] = t0.y; R[2] = t1.x; R[3] = t1.y; R[4] = base[4];
}

// one dy step: 5 dx x 9 k x (2 rows x 1 colpair)
__device__ __forceinline__ void conv9(const ull* __restrict__ wrow,
                                      const ull (&R)[5], const ull (&S)[5],
                                      ull (&acc)[9][2])
{
#pragma unroll
    for (int dx = 0; dx < 5; dx++) {
        const ull* wp = wrow + dx * 12;
        ulonglong2 t0 = *reinterpret_cast<const ulonglong2*>(wp);
        ulonglong2 t1 = *reinterpret_cast<const ulonglong2*>(wp + 2);
        ulonglong2 t2 = *reinterpret_cast<const ulonglong2*>(wp + 4);
        ulonglong2 t3 = *reinterpret_cast<const ulonglong2*>(wp + 6);
        ull w8v = wp[8];
        ull w[9];
        w[0] = t0.x; w[1] = t0.y; w[2] = t1.x; w[3] = t1.y;
        w[4] = t2.x; w[5] = t2.y; w[6] = t3.x; w[7] = t3.y; w[8] = w8v;
#pragma unroll
        for (int k = 0; k < 9; k++) {
            acc[k][0] = fma2(R[dx], w[k], acc[k][0]);
            acc[k][1] = fma2(S[dx], w[k], acc[k][1]);
        }
    }
}

// ---------------------------------------------------------------------------
// main + border fused. 256 threads/block, thread = 2 rows x 2 cols.
// ---------------------------------------------------------------------------
__global__ __launch_bounds__(256) void smmain_kernel(
    const float* __restrict__ img0, const float* __restrict__ img1p, const float* __restrict__ img2p,
    const float* __restrict__ xin0, const float* __restrict__ xin1, const float* __restrict__ xin2,
    float* __restrict__ out0, float* __restrict__ out1, float* __restrict__ out2,
    const ull* __restrict__ tabDup, const ull* __restrict__ tabBDup,
    const float* __restrict__ tabW5, const float* __restrict__ tabB,
    int nc_in, int slotBase, int mode)
{
    const int bx = blockIdx.x;
    const int o = blockIdx.y, b = blockIdx.z;
    const int tid = threadIdx.x;
    const int mainX = (mode == 0) ? 16 : 21;

    if (bx >= mainX) {
        // ---------------- border path ----------------
        int bp = (bx - mainX) * 256 + tid;
        int limit = (mode == 0) ? 508 : 884;
        if (bp >= limit) return;
        int s, e;
        if (bp < 508)      { s = 0; e = bp; }
        else if (bp < 760) { s = 1; e = bp - 508; }
        else               { s = 2; e = bp - 760; }
        const float* img = (s == 0) ? img0 : (s == 1) ? img1p : img2p;
        const float* xin = (s == 0) ? xin0 : (s == 1) ? xin1 : xin2;
        float* out = (s == 0) ? out0 : (s == 1) ? out1 : out2;
        const int N = 128 >> s;
        const int slot = slotBase + s;

        int py, px;
        if (e < N)              { py = 0;     px = e; }
        else if (e < 2 * N)     { py = N - 1; px = e - N; }
        else if (e < 3 * N - 2) { py = e - 2 * N + 1;       px = 0; }
        else                    { py = e - (3 * N - 2) + 1; px = N - 1; }

        bool Tt = (py == 0), Bb = (py == N - 1), Ll = (px == 0), Rr = (px == N - 1);
        int cls = Tt ? (Ll ? 5 : (Rr ? 6 : 1))
                     : (Bb ? (Ll ? 7 : (Rr ? 8 : 2)) : (Ll ? 3 : 4));

        float w[25];
        const float* ibp = img + (size_t)b * N * N;
#pragma unroll
        for (int dy = 0; dy < 5; dy++)
#pragma unroll
            for (int dx = 0; dx < 5; dx++) {
                int iy = py - 2 + dy, ix = px - 2 + dx;
                w[dy * 5 + dx] = (iy >= 0 && iy < N && ix >= 0 && ix < N) ? ibp[iy * N + ix] : 0.f;
            }

        float accv = 0.f;
        for (int i = 0; i < nc_in; i++) {
            int g = o * nc_in + i;
            const float* tb = tabW5 + (size_t)slot * 129600 + ((size_t)(cls * 64 + g) * 9) * 25;
            const float* bb = tabB + (size_t)slot * 5184 + (size_t)(cls * 64 + g) * 9;
            const float* xb = xin + ((size_t)b * nc_in + i) * N * N;
            float Kf[9];
#pragma unroll
            for (int k = 0; k < 9; k++) Kf[k] = bb[k];
#pragma unroll
            for (int j = 0; j < 25; j++) {
                float v = w[j];
#pragma unroll
                for (int k = 0; k < 9; k++) Kf[k] += tb[k * 25 + j] * v;
            }
#pragma unroll
            for (int k = 0; k < 9; k++) {
                int yy = py + k / 3 - 1, xx = px + k % 3 - 1;
                float xv = (yy >= 0 && yy < N && xx >= 0 && xx < N) ? xb[yy * N + xx] : 0.f;
                accv += Kf[k] * xv;
            }
        }
        out[((size_t)b * NC + o) * N * N + py * N + px] = elu_f(accv);
        return;
    }

    // ---------------- main (interior) path ----------------
    __shared__ __align__(16) ull   spair[36 * 36];         // 10368 B
    __shared__ __align__(16) float sxs[CHG * 34 * 36];     // 19584 B
    __shared__ __align__(16) ull   sWd[CHG * 300];         // 9600 B
    __shared__ __align__(16) ull   sBd[CHG * 12];          // 384 B  -> ~40 KB

    int s, tile;
    const float *img, *xin;
    float* out;
    if (bx < 16)      { s = 0; tile = bx;      img = img0;  xin = xin0; out = out0; }
    else if (bx < 20) { s = 1; tile = bx - 16; img = img1p; xin = xin1; out = out1; }
    else              { s = 2; tile = bx - 20; img = img2p; xin = xin2; out = out2; }
    const int N = 128 >> s;
    const int tilesX = N / 32;
    const int tx0 = (tile % tilesX) * 32, ty0 = (tile / tilesX) * 32;
    const int slot = slotBase + s;
    const int pqx = (tid & 15) * 2;   // 2 cols per thread (even)
    const int pqy = (tid >> 4) * 2;   // 2 rows per thread

    // build packed adjacent-pair image tile straight from gmem (zero-padded)
    const float* ib = img + (size_t)b * N * N;
    for (int idx = tid; idx < 36 * 35; idx += 256) {
        int ly = idx / 35, lx = idx % 35;
        int gy = ty0 - 2 + ly, gx = tx0 - 2 + lx;
        bool iny = (gy >= 0 && gy < N);
        float v0 = (iny && gx >= 0 && gx < N) ? ib[gy * N + gx] : 0.f;
        float v1 = (iny && gx + 1 >= 0 && gx + 1 < N) ? ib[gy * N + gx + 1] : 0.f;
        spair[ly * 36 + lx] = pk(v0, v1);
    }
    // (sync provided by the per-phase post-load barrier)

    ull oacc[2];
    oacc[0] = 0ull; oacc[1] = 0ull;

    for (int i0 = 0; i0 < nc_in; i0 += CHG) {
        const int chg = (nc_in - i0 < CHG) ? (nc_in - i0) : CHG;
        __syncthreads();   // previous phase compute done (and spair build, phase 0)

        // stage chg channels: x tiles, weights, biases
        for (int idx = tid; idx < chg * 1156; idx += 256) {
            int ci = idx / 1156, r = idx % 1156;
            int ly = r / 34, lx = r % 34;
            int gy = ty0 - 1 + ly, gx = tx0 - 1 + lx;
            const float* xb = xin + ((size_t)b * nc_in + (i0 + ci)) * N * N;
            sxs[ci * 1224 + ly * 36 + lx] =
                (gy >= 0 && gy < N && gx >= 0 && gx < N) ? xb[gy * N + gx] : 0.f;
        }
        for (int idx = tid; idx < chg * 300; idx += 256) {
            int ci = idx / 300, j = idx % 300;
            int g = o * nc_in + i0 + ci;
            sWd[ci * 300 + j] = tabDup[(size_t)slot * 19200 + (size_t)g * 300 + j];
        }
        if (tid < chg * 12) {
            int ci = tid / 12, j = tid % 12;
            int g = o * nc_in + i0 + ci;
            sBd[ci * 12 + j] = tabBDup[(size_t)slot * 768 + (size_t)g * 12 + j];
        }
        __syncthreads();

#pragma unroll 1
        for (int ci = 0; ci < chg; ci++) {
            const ull*   wd = sWd + ci * 300;
            const ull*   bd = sBd + ci * 12;
            const float* xc = sxs + ci * 1224;

            ull acc[9][2];
#pragma unroll
            for (int k = 0; k < 9; k++) {
                ull bb = bd[k];
                acc[k][0] = bb; acc[k][1] = bb;
            }

            ull A[5], B[5];
            load_row5(spair, pqy,     pqx, A);
            load_row5(spair, pqy + 1, pqx, B);
            conv9(wd,       A, B, acc);
            load_row5(spair, pqy + 2, pqx, A);
            conv9(wd + 60,  B, A, acc);
            load_row5(spair, pqy + 3, pqx, B);
            conv9(wd + 120, A, B, acc);
            load_row5(spair, pqy + 4, pqx, A);
            conv9(wd + 180, B, A, acc);
            load_row5(spair, pqy + 5, pqx, B);
            conv9(wd + 240, A, B, acc);

            // apply: per (rr,ky) stream one x row (3-ull live window)
#pragma unroll
            for (int rr = 0; rr < 2; rr++) {
#pragma unroll
                for (int ky = 0; ky < 3; ky++) {
                    const float* xr = xc + (pqy + rr + ky) * 36 + pqx;
                    float2 a2 = *reinterpret_cast<const float2*>(xr);
                    float2 b2 = *reinterpret_cast<const float2*>(xr + 2);
                    oacc[rr] = fma2(acc[ky * 3 + 0][rr], pk(a2.x, a2.y), oacc[rr]);
                    oacc[rr] = fma2(acc[ky * 3 + 1][rr], pk(a2.y, b2.x), oacc[rr]);
                    oacc[rr] = fma2(acc[ky * 3 + 2][rr], pk(b2.x, b2.y), oacc[rr]);
                }
            }
        }
    }

    float* ob = out + ((size_t)b * NC + o) * N * N;
#pragma unroll
    for (int sy = 0; sy < 2; sy++) {
        float lo, hi;
        upk(oacc[sy], lo, hi);
        int row = ty0 + pqy + sy, col = tx0 + pqx;
        if (row > 0 && row < N - 1) {
            if (col > 0 && col < N - 1)         ob[row * N + col]     = elu_f(lo);
            if (col + 1 > 0 && col + 1 < N - 1) ob[row * N + col + 1] = elu_f(hi);
        }
    }
}

// ---------------------------------------------------------------------------
__global__ void down_kernel(const float* __restrict__ in, float* __restrict__ out,
                            int C, int No)
{
    int idx = blockIdx.x * blockDim.x + threadIdx.x;
    int total = C * No * No;
    if (idx >= total) return;
    int c = idx / (No * No);
    int p = idx % (No * No);
    int h = p / No, w = p % No;
    int Ni = No * 2;
    const float* ib = in + (size_t)c * Ni * Ni;
    float sv = ib[(2 * h) * Ni + 2 * w] + ib[(2 * h) * Ni + 2 * w + 1]
             + ib[(2 * h + 1) * Ni + 2 * w] + ib[(2 * h + 1) * Ni + 2 * w + 1];
    out[idx] = 0.25f * sv;
}

__global__ void combine_kernel(const float* __restrict__ x0,
                               const float* __restrict__ x1,
                               const float* __restrict__ x2,
                               const float* __restrict__ w5, const float* __restrict__ b5,
                               const float* __restrict__ w6, const float* __restrict__ b6,
                               float* __restrict__ out)
{
    int idx = blockIdx.x * blockDim.x + threadIdx.x;
    if (idx >= 8 * 128 * 128) return;
    int b = idx / (128 * 128);
    int p = idx % (128 * 128);
    int h = p / 128, w = p % 128;
    float v[NC];
#pragma unroll
    for (int c = 0; c < NC; c++) {
        v[c] = x0[((size_t)b * NC + c) * 16384 + p]
             + x1[((size_t)b * NC + c) * 4096 + (h >> 1) * 64 + (w >> 1)]
             + x2[((size_t)b * NC + c) * 1024 + (h >> 2) * 32 + (w >> 2)];
    }
    float accv = b6[0];
#pragma unroll
    for (int o = 0; o < NC; o++) {
        float y = b5[o];
#pragma unroll
        for (int c = 0; c < NC; c++) y += w5[o * NC + c] * v[c];
        y = elu_f(y);
        accv += w6[o] * y;
    }
    out[idx] = accv;
}

// ---------------------------------------------------------------------------
extern "C" void kernel_launch(void* const* d_in, const int* in_sizes, int n_in,
                              void* d_out, int out_size)
{
    const float* image = (const float*)d_in[0];
    const float* x_in  = (const float*)d_in[1];
    const float* iW1   = (const float*)d_in[2];
    const float* ib1   = (const float*)d_in[3];
    const float* iW2   = (const float*)d_in[4];
    const float* ib2   = (const float*)d_in[5];
    const float* bW1   = (const float*)d_in[6];
    const float* bb1   = (const float*)d_in[7];
    const float* bW2   = (const float*)d_in[8];
    const float* bb2   = (const float*)d_in[9];
    const float* w5    = (const float*)d_in[10];
    const float* b5    = (const float*)d_in[11];
    const float* w6    = (const float*)d_in[12];
    const float* b6    = (const float*)d_in[13];

    float* base;
    cudaGetSymbolAddress((void**)&base, g_buf);
    float* img1 = base;
    float* img2 = img1 + 32768;
    float* x0a  = img2 + 8192;
    float* x0b  = x0a + 1048576;
    float* x1a  = x0b + 1048576;
    float* x1b  = x1a + 262144;
    float* x2a  = x1b + 262144;
    float* x2b  = x2a + 65536;
    float* tabW5 = x2b + 65536;                // 13*129600
    float* tabB  = tabW5 + 13 * 129600;        // 13*5184
    ull*   tabDup  = (ull*)(tabB + 13 * 5184); // 13*19200 ull
    ull*   tabBDup = tabDup + 13 * 19200;      // 13*768 ull

    // all tables upfront (x-independent)
    compose_kernel<<<(13 * 5184 + 127) / 128, 128>>>(
        iW1, ib1, iW2, ib2, bW1, bb1, bW2, bb2, tabW5, tabB, tabDup, tabBDup);

    // image pyramid
    down_kernel<<<(8 * 64 * 64 + 255) / 256, 256>>>(image, img1, 8, 64);
    down_kernel<<<(8 * 32 * 32 + 255) / 256, 256>>>(img1, img2, 8, 32);

    // init block (slot 0, nc_in=1, full-res only) with fused border
    smmain_kernel<<<dim3(18, 8, 8), 256>>>(image, img1, img2,
        x_in, x_in, x_in, x0a, x0a, x0a, tabDup, tabBDup, tabW5, tabB, 1, 0, 0);

    // downsample x
    down_kernel<<<(64 * 64 * 64 + 255) / 256, 256>>>(x0a, x1a, 64, 64);
    down_kernel<<<(64 * 32 * 32 + 255) / 256, 256>>>(x1a, x2a, 64, 32);

    float *xc = x0a, *xn = x0b;
    float *x1c = x1a, *x1n = x1b;
    float *x2c = x2a, *x2n = x2b;

    for (int t = 0; t < 4; t++) {
        smmain_kernel<<<dim3(25, 8, 8), 256>>>(image, img1, img2,
            xc, x1c, x2c, xn, x1n, x2n, tabDup, tabBDup, tabW5, tabB,
            8, 1 + 3 * t, 1);
        { float* tp = xc;  xc = xn;   xn = tp; }
        { float* tp = x1c; x1c = x1n; x1n = tp; }
        { float* tp = x2c; x2c = x2n; x2n = tp; }
    }

    combine_kernel<<<(8 * 128 * 128 + 255) / 256, 256>>>(
        xc, x1c, x2c, w5, b5, w6, b6, (float*)d_out);
}